// round 5
// baseline (speedup 1.0000x reference)
#include <cuda_runtime.h>
#include <cstdint>

// SDDMM: out[i] = mask_vals[i] + dot(mat1[rows[i], :], mat2[:, cols[i]])
// Inputs: mask_vals f32[1e6], rows i32[1e6], cols i32[1e6],
//         mat1 f32[8192,128], mat2 f32[128,8192]   Output: f32[1e6]

#define NNZ  1000000
#define MDIM 8192
#define NDIM 8192
#define KDIM 128

// Scratch (all static __device__; no allocations anywhere)
__device__ float g_mat2T[(size_t)NDIM * KDIM];   // mat2 transposed [N, K]
__device__ int   g_cursor[MDIM];                 // scan result / scatter cursors
__device__ int   g_count[MDIM];                  // histogram
__device__ int   g_rs[NNZ];                      // rows, sorted by row
__device__ int   g_cs[NNZ];                      // cols, in row-sorted order
__device__ int   g_perm[NNZ];                    // original nnz index

// ---------------------------------------------------------------------------
// Transpose mat2 [K, N] -> g_mat2T [N, K]
// ---------------------------------------------------------------------------
__global__ void transpose_k(const float* __restrict__ mat2) {
    __shared__ float tile[32][33];
    const int n0 = blockIdx.x * 32;
    const int k0 = blockIdx.y * 32;
    #pragma unroll
    for (int r = threadIdx.y; r < 32; r += 8)
        tile[r][threadIdx.x] = mat2[(size_t)(k0 + r) * NDIM + n0 + threadIdx.x];
    __syncthreads();
    #pragma unroll
    for (int r = threadIdx.y; r < 32; r += 8)
        g_mat2T[(size_t)(n0 + r) * KDIM + k0 + threadIdx.x] = tile[threadIdx.x][r];
}

// ---------------------------------------------------------------------------
// Counting sort by row: zero -> histogram -> scan -> scatter
// ---------------------------------------------------------------------------
__global__ void zero_k() {
    g_count[blockIdx.x * blockDim.x + threadIdx.x] = 0;
}

__global__ void hist_k(const int* __restrict__ rows) {
    const int i = blockIdx.x * blockDim.x + threadIdx.x;
    if (i < NNZ) atomicAdd(&g_count[rows[i]], 1);
}

// Exclusive scan of g_count[8192] -> g_cursor. One block, 1024 threads x 8.
__global__ void scan_k() {
    __shared__ int sh[1024];
    const int t = threadIdx.x;
    int local[8];
    int s = 0;
    #pragma unroll
    for (int j = 0; j < 8; j++) { local[j] = s; s += g_count[t * 8 + j]; }
    sh[t] = s;
    __syncthreads();
    // Hillis-Steele inclusive scan over the 1024 partials
    for (int off = 1; off < 1024; off <<= 1) {
        int v = (t >= off) ? sh[t - off] : 0;
        __syncthreads();
        sh[t] += v;
        __syncthreads();
    }
    const int base = (t == 0) ? 0 : sh[t - 1];
    #pragma unroll
    for (int j = 0; j < 8; j++) g_cursor[t * 8 + j] = base + local[j];
}

__global__ void scatter_k(const int* __restrict__ rows,
                          const int* __restrict__ cols) {
    const int i = blockIdx.x * blockDim.x + threadIdx.x;
    if (i >= NNZ) return;
    const int r = rows[i];
    const int p = atomicAdd(&g_cursor[r], 1);
    g_rs[p]   = r;
    g_cs[p]   = cols[i];
    g_perm[p] = i;
}

// ---------------------------------------------------------------------------
// SDDMM over row-sorted nnz: 8 lanes per nnz, 4 nnz per warp-iteration.
// Consecutive nnz share rows -> row LDGs hit the same lines (L1/wavefront
// dedup); column gathers remain the only bulk L2 traffic.
// ---------------------------------------------------------------------------
__global__ void __launch_bounds__(256)
sddmm_k(const float* __restrict__ mask_vals,
        const float* __restrict__ mat1,
        float* __restrict__ out) {
    const int lane   = threadIdx.x & 31;
    const int sub    = lane & 7;
    const int grp    = lane >> 3;
    const int gwarp  = (blockIdx.x * blockDim.x + threadIdx.x) >> 5;
    const int nwarps = (gridDim.x * blockDim.x) >> 5;

    for (int base = gwarp * 4; base < NNZ; base += nwarps * 4) {
        const int j = base + grp;
        const int r = g_rs[j];          // broadcast within the 8-lane group
        const int c = g_cs[j];
        const int i = g_perm[j];        // original position

        const float4* __restrict__ a4 =
            reinterpret_cast<const float4*>(mat1 + (size_t)r * KDIM);
        const float4* __restrict__ b4 =
            reinterpret_cast<const float4*>(g_mat2T + (size_t)c * KDIM);

        const float4 a0 = a4[sub];
        const float4 b0 = b4[sub];
        const float4 a1 = a4[sub + 8];
        const float4 b1 = b4[sub + 8];
        const float4 a2 = a4[sub + 16];
        const float4 b2 = b4[sub + 16];
        const float4 a3 = a4[sub + 24];
        const float4 b3 = b4[sub + 24];

        float s = a0.x * b0.x;
        s = fmaf(a0.y, b0.y, s); s = fmaf(a0.z, b0.z, s); s = fmaf(a0.w, b0.w, s);
        s = fmaf(a1.x, b1.x, s); s = fmaf(a1.y, b1.y, s);
        s = fmaf(a1.z, b1.z, s); s = fmaf(a1.w, b1.w, s);
        s = fmaf(a2.x, b2.x, s); s = fmaf(a2.y, b2.y, s);
        s = fmaf(a2.z, b2.z, s); s = fmaf(a2.w, b2.w, s);
        s = fmaf(a3.x, b3.x, s); s = fmaf(a3.y, b3.y, s);
        s = fmaf(a3.z, b3.z, s); s = fmaf(a3.w, b3.w, s);

        s += __shfl_xor_sync(0xFFFFFFFFu, s, 4);
        s += __shfl_xor_sync(0xFFFFFFFFu, s, 2);
        s += __shfl_xor_sync(0xFFFFFFFFu, s, 1);

        if (sub == 0)
            out[i] = mask_vals[i] + s;
    }
}

extern "C" void kernel_launch(void* const* d_in, const int* in_sizes, int n_in,
                              void* d_out, int out_size) {
    const float* mask_vals = (const float*)d_in[0];
    const int*   rows      = (const int*)d_in[1];
    const int*   cols      = (const int*)d_in[2];
    const float* mat1      = (const float*)d_in[3];
    const float* mat2      = (const float*)d_in[4];
    float*       out       = (float*)d_out;

    // Transpose mat2 into scratch
    dim3 tgrid(NDIM / 32, KDIM / 32);
    transpose_k<<<tgrid, dim3(32, 8)>>>(mat2);

    // Counting sort by row
    zero_k<<<MDIM / 256, 256>>>();
    hist_k<<<(NNZ + 255) / 256, 256>>>(rows);
    scan_k<<<1, 1024>>>();
    scatter_k<<<(NNZ + 255) / 256, 256>>>(rows, cols);

    // SDDMM over sorted order
    sddmm_k<<<148 * 8, 256>>>(mask_vals, mat1, out);
}